// round 9
// baseline (speedup 1.0000x reference)
#include <cuda_runtime.h>
#include <math.h>

#define GN     6
#define GC     7       // clamped grid side (row/col 6 = trash)
#define NROW   (GC*GC) // 49 histogram rows
#define NCELL  36
#define HID    128
#define NT     64      // threads per block (pair kernel)
#define APB    (2*NT)  // agents per block = 128 (2 per thread)
#define SEG    64      // j-segments -> grid 4096 when N=8192 (1.7 waves @16 blk/SM)
#define TJ     128     // j tile size (== 8192/SEG when N==MAXN)
#define MAXN   8192
#define BI     32      // rows per block in GEMM kernel

// Partial occupancy planes, uint16: [seg][cell][i] (count per segment <= TJ=128)
__device__ unsigned short g_part[SEG * NCELL * MAXN];
// Reduced occupancy, transposed float: [cell][i]
__device__ float g_occ[NCELL * MAXN];

// rx, ry are precombined grid coords (tile holds 2*xj+3; thread holds -2*xi; one
// FADD joins them). Clamp-grid trash: min((unsigned)floor, 6) sends every invalid
// coordinate (negative -> unsigned-huge, >=6, or saturated F2I from the +1e30
// sentinels) to row/col 6. No predicates, no branches.
// Histogram u32, conflict-free (bank = tid%32): agent A in low 16 bits (inc=1),
// agent B in high 16 bits (inc=1<<16); counts <= 128 so halves never carry.
__device__ __forceinline__ void bump(unsigned* occ, int tid, float rx, float ry,
                                     unsigned inc) {
    unsigned ix = umin((unsigned)__float2int_rd(rx), (unsigned)(GC - 1));
    unsigned iy = umin((unsigned)__float2int_rd(ry), (unsigned)(GC - 1));
    occ[(ix * GC + iy) * NT + tid] += inc;
}

template<bool EXACT>
__global__ __launch_bounds__(NT, 16)
void occ_pair_kernel(const float2* __restrict__ obs, int N) {
    __shared__ __align__(16) float2 tile[TJ];    // holds (2*xj+3, 2*yj+3)
    __shared__ unsigned occ[NROW * NT];

    const int tid = threadIdx.x;
    const int iA  = blockIdx.x * APB + tid;
    const int iB  = iA + NT;
    const int seg = blockIdx.y;
    const int JS  = EXACT ? (MAXN / SEG) : ((N + SEG - 1) / SEG);
    const int j0  = seg * JS;
    const int j1  = EXACT ? (j0 + JS) : min(j0 + JS, N);

    // Hold -2*x_i (exact: *2 exact, negate exact). Invalid -> +1e30 sentinel.
    float nxA = 1e30f, nyA = 1e30f, nxB = 1e30f, nyB = 1e30f;
    if (iA < N) {
        float2 p = obs[iA];
        if (!isnan(p.x) && !isnan(p.y)) { nxA = -2.0f * p.x; nyA = -2.0f * p.y; }
    }
    if (iB < N) {
        float2 p = obs[iB];
        if (!isnan(p.x) && !isnan(p.y)) { nxB = -2.0f * p.x; nyB = -2.0f * p.y; }
    }

    #pragma unroll
    for (int c = 0; c < NROW; c++) occ[c * NT + tid] = 0;
    __syncthreads();

    for (int jb = j0; jb < j1; jb += TJ) {
        const int nj = EXACT ? TJ : min(TJ, j1 - jb);
        for (int t = tid; t < nj; t += NT) {
            float2 p = obs[jb + t];
            float2 v;
            if (isnan(p.x) || isnan(p.y)) { v.x = 1e30f; v.y = 1e30f; }
            else { v.x = fmaf(p.x, 2.0f, 3.0f); v.y = fmaf(p.y, 2.0f, 3.0f); }
            tile[t] = v;
        }
        __syncthreads();

        // Two j's per LDS.128 broadcast; one FADD per coordinate per pair.
        const float4* t4 = (const float4*)tile;
        const int nj2 = nj >> 1;
        #pragma unroll 4
        for (int jj = 0; jj < nj2; jj++) {
            const float4 q = t4[jj];
            bump(occ, tid, q.x + nxA, q.y + nyA, 1u);
            bump(occ, tid, q.x + nxB, q.y + nyB, 1u << 16);
            bump(occ, tid, q.z + nxA, q.w + nyA, 1u);
            bump(occ, tid, q.z + nxB, q.w + nyB, 1u << 16);
        }
        if (!EXACT && (nj & 1)) {
            const float2 p = tile[nj - 1];
            bump(occ, tid, p.x + nxA, p.y + nyA, 1u);
            bump(occ, tid, p.x + nxB, p.y + nyB, 1u << 16);
        }
        __syncthreads();
    }

    // Store the 36 real cells (skip clamp row/col 6).
    if (iA < N) {
        #pragma unroll
        for (int c = 0; c < NCELL; c++) {
            const int row = (c / GN) * GC + (c % GN);
            g_part[(seg * NCELL + c) * N + iA] =
                (unsigned short)(occ[row * NT + tid] & 0xFFFFu);
        }
    }
    if (iB < N) {
        #pragma unroll
        for (int c = 0; c < NCELL; c++) {
            const int row = (c / GN) * GC + (c % GN);
            g_part[(seg * NCELL + c) * N + iB] =
                (unsigned short)(occ[row * NT + tid] >> 16);
        }
    }
}

// Segment reduction: one thread per (cell, 8 agents); packed uint16 adds.
__global__ __launch_bounds__(256)
void occ_reduce_kernel(int N) {
    const int nI8 = N >> 3;
    const int t   = blockIdx.x * 256 + threadIdx.x;
    if (t >= NCELL * nI8) return;
    const int c = t / nI8;
    const int i = (t - c * nI8) * 8;

    uint4 acc = make_uint4(0u, 0u, 0u, 0u);
    #pragma unroll 8
    for (int sg = 0; sg < SEG; sg++) {
        const uint4 v = *reinterpret_cast<const uint4*>(
            &g_part[(sg * NCELL + c) * N + i]);          // 8 uint16 per LDG.128
        acc.x = __vadd2(acc.x, v.x);                     // sums <= N < 2^16
        acc.y = __vadd2(acc.y, v.y);
        acc.z = __vadd2(acc.z, v.z);
        acc.w = __vadd2(acc.w, v.w);
    }
    float4 lo, hi;
    lo.x = (float)(acc.x & 0xFFFFu); lo.y = (float)(acc.x >> 16);
    lo.z = (float)(acc.y & 0xFFFFu); lo.w = (float)(acc.y >> 16);
    hi.x = (float)(acc.z & 0xFFFFu); hi.y = (float)(acc.z >> 16);
    hi.z = (float)(acc.w & 0xFFFFu); hi.w = (float)(acc.w >> 16);
    *reinterpret_cast<float4*>(&g_occ[c * N + i])     = lo;
    *reinterpret_cast<float4*>(&g_occ[c * N + i + 4]) = hi;
}

// Generic-N fallback reduction (scalar).
__global__ __launch_bounds__(256)
void occ_reduce_generic(int N) {
    const int t = blockIdx.x * 256 + threadIdx.x;
    if (t >= NCELL * N) return;
    const int c = t / N;
    const int i = t - c * N;
    unsigned s = 0;
    #pragma unroll 8
    for (int sg = 0; sg < SEG; sg++)
        s += g_part[(sg * NCELL + c) * N + i];
    g_occ[c * N + i] = (float)s;
}

// [N,36] x [36,128] GEMM with smem-staged W and broadcast occ reads.
__global__ __launch_bounds__(256)
void occ_gemm_kernel(const float2* __restrict__ obs,
                     const float*  __restrict__ W,
                     const float*  __restrict__ b,
                     float*        __restrict__ out, int N) {
    __shared__ float sW[HID * 37];                   // stride 37: 5h+c mod 32 conflict-free
    __shared__ __align__(16) float occ_s[BI][40];    // row stride 40: float4-aligned
    __shared__ float sself[BI];

    const int tid = threadIdx.x;
    const int i0  = blockIdx.x * BI;

    // Stage W coalesced.
    for (int idx = tid; idx < HID * NCELL; idx += 256) {
        const int h = idx / NCELL;
        sW[h * 37 + (idx - h * NCELL)] = W[idx];
    }
    // Load occ tile (coalesced along i from the [cell][i] layout).
    for (int idx = tid; idx < NCELL * BI; idx += 256) {
        const int c = idx >> 5, l = idx & 31;
        const int i = i0 + l;
        occ_s[l][c] = (i < N) ? g_occ[c * N + i] : 0.f;
    }
    if (tid < BI) {
        const int i = i0 + tid;
        float v = 0.f;
        if (i < N) {
            const float2 p = obs[i];
            if (!isnan(p.x) && !isnan(p.y)) v = 1.f;
        }
        sself[tid] = v;
    }
    __syncthreads();

    const int h = tid & (HID - 1);
    float w[NCELL];
    #pragma unroll
    for (int c = 0; c < NCELL; c++) w[c] = sW[h * 37 + c];
    const float bias = b[h];

    const int il0 = (tid >> 7) * (BI / 2);
    #pragma unroll
    for (int r = 0; r < BI / 2; r++) {
        const int il = il0 + r;
        const int i  = i0 + il;
        if (i >= N) break;
        // Self-pair was counted at cell 21 iff agent i is finite; remove it.
        float acc = fmaf(-sself[il], w[21], bias);
        const float4* row = (const float4*)&occ_s[il][0];
        #pragma unroll
        for (int c4 = 0; c4 < 9; c4++) {
            const float4 v = row[c4];     // broadcast LDS.128
            acc = fmaf(v.x, w[c4 * 4 + 0], acc);
            acc = fmaf(v.y, w[c4 * 4 + 1], acc);
            acc = fmaf(v.z, w[c4 * 4 + 2], acc);
            acc = fmaf(v.w, w[c4 * 4 + 3], acc);
        }
        out[i * HID + h] = acc;
    }
}

extern "C" void kernel_launch(void* const* d_in, const int* in_sizes, int n_in,
                              void* d_out, int out_size) {
    const float2* obs = (const float2*)d_in[0];
    const float*  W   = (const float*)d_in[1];
    const float*  b   = (const float*)d_in[2];
    float*        out = (float*)d_out;
    const int N = in_sizes[0] / 2;

    if (N == MAXN) {
        dim3 g1(MAXN / APB, SEG);
        occ_pair_kernel<true><<<g1, NT>>>(obs, N);
    } else {
        dim3 g1((N + APB - 1) / APB, SEG);
        occ_pair_kernel<false><<<g1, NT>>>(obs, N);
    }
    if ((N & 7) == 0) {
        const int rthreads = NCELL * (N >> 3);
        occ_reduce_kernel<<<(rthreads + 255) / 256, 256>>>(N);
    } else {
        const int rthreads = NCELL * N;
        occ_reduce_generic<<<(rthreads + 255) / 256, 256>>>(N);
    }
    occ_gemm_kernel<<<(N + BI - 1) / BI, 256>>>(obs, W, b, out, N);
}

// round 10
// speedup vs baseline: 1.0348x; 1.0348x over previous
#include <cuda_runtime.h>
#include <math.h>

#define GN     6
#define GC     7       // clamped grid side (row/col 6 = trash)
#define NROW   (GC*GC) // 49 histogram rows
#define NCELL  36
#define HID    128
#define NT     64      // threads per block (pair kernel)
#define APB    (2*NT)  // agents per block = 128 (2 per thread)
#define SEG    64      // j-segments -> grid 4096 when N=8192
#define TJ     128     // j tile size; counts per segment <= 128 -> fit in u8
#define MAXN   8192
#define BI     32      // rows per block in GEMM kernel

// Packed partials: [seg][cell][k] u16 = (countA:u8) | (countB:u8 << 8),
// where pair k -> agents iA = (k>>6)*128 + (k&63), iB = iA + 64.
__device__ unsigned short g_part[SEG * NCELL * (MAXN / 2)];
// Reduced occupancy, transposed float: [cell][i]
__device__ float g_occ[NCELL * MAXN];

// rx, ry are precombined grid coords (tile holds 2*xj+3; thread holds -2*xi; one
// FADD joins them). Clamp-grid trash: min((unsigned)floor, 6) sends every invalid
// coordinate (negative -> unsigned-huge, >=6, or saturated F2I from the +1e30
// sentinels) to row/col 6. No predicates, no branches.
// Histogram u32, conflict-free (bank = tid%32): agent A at bit 0, agent B at
// bit 16; per-segment counts <= 128 so each field stays within 8 bits.
__device__ __forceinline__ void bump(unsigned* occ, int tid, float rx, float ry,
                                     unsigned inc) {
    unsigned ix = umin((unsigned)__float2int_rd(rx), (unsigned)(GC - 1));
    unsigned iy = umin((unsigned)__float2int_rd(ry), (unsigned)(GC - 1));
    occ[(ix * GC + iy) * NT + tid] += inc;
}

template<bool EXACT>
__global__ __launch_bounds__(NT, 16)
void occ_pair_kernel(const float2* __restrict__ obs, int N, int NP) {
    __shared__ __align__(16) float2 tile[TJ];    // holds (2*xj+3, 2*yj+3)
    __shared__ unsigned occ[NROW * NT];

    const int tid = threadIdx.x;
    const int iA  = blockIdx.x * APB + tid;
    const int iB  = iA + NT;
    const int seg = blockIdx.y;
    const int JS  = EXACT ? (MAXN / SEG) : ((N + SEG - 1) / SEG);
    const int j0  = seg * JS;
    const int j1  = EXACT ? (j0 + JS) : min(j0 + JS, N);

    // Hold -2*x_i (exact: *2 exact, negate exact). Invalid -> +1e30 sentinel:
    // all counts land in clamp rows, real cells stay 0.
    float nxA = 1e30f, nyA = 1e30f, nxB = 1e30f, nyB = 1e30f;
    if (iA < N) {
        float2 p = obs[iA];
        if (!isnan(p.x) && !isnan(p.y)) { nxA = -2.0f * p.x; nyA = -2.0f * p.y; }
    }
    if (iB < N) {
        float2 p = obs[iB];
        if (!isnan(p.x) && !isnan(p.y)) { nxB = -2.0f * p.x; nyB = -2.0f * p.y; }
    }

    #pragma unroll
    for (int c = 0; c < NROW; c++) occ[c * NT + tid] = 0;
    __syncthreads();

    for (int jb = j0; jb < j1; jb += TJ) {
        const int nj = EXACT ? TJ : min(TJ, j1 - jb);
        for (int t = tid; t < nj; t += NT) {
            float2 p = obs[jb + t];
            float2 v;
            if (isnan(p.x) || isnan(p.y)) { v.x = 1e30f; v.y = 1e30f; }
            else { v.x = fmaf(p.x, 2.0f, 3.0f); v.y = fmaf(p.y, 2.0f, 3.0f); }
            tile[t] = v;
        }
        __syncthreads();

        // Two j's per LDS.128 broadcast; one FADD per coordinate per pair.
        const float4* t4 = (const float4*)tile;
        const int nj2 = nj >> 1;
        #pragma unroll 4
        for (int jj = 0; jj < nj2; jj++) {
            const float4 q = t4[jj];
            bump(occ, tid, q.x + nxA, q.y + nyA, 1u);
            bump(occ, tid, q.x + nxB, q.y + nyB, 1u << 16);
            bump(occ, tid, q.z + nxA, q.w + nyA, 1u);
            bump(occ, tid, q.z + nxB, q.w + nyB, 1u << 16);
        }
        if (!EXACT && (nj & 1)) {
            const float2 p = tile[nj - 1];
            bump(occ, tid, p.x + nxA, p.y + nyA, 1u);
            bump(occ, tid, p.x + nxB, p.y + nyB, 1u << 16);
        }
        __syncthreads();
    }

    // Store 36 real cells packed: (A count u8) | (B count u8 << 8). OOB agents
    // contributed only to clamp rows, so their real cells are 0 -> safe.
    const int k = blockIdx.x * NT + tid;
    #pragma unroll
    for (int c = 0; c < NCELL; c++) {
        const int row = (c / GN) * GC + (c % GN);
        const unsigned v = occ[row * NT + tid];
        g_part[(seg * NCELL + c) * NP + k] =
            (unsigned short)((v & 0xFFu) | ((v >> 8) & 0xFF00u));
    }
}

// Vector reduction (N % 128 == 0): thread per (cell, 8 pair-slots).
// Sums packed u8 pairs with masked vadd2 (halfword sums <= SEG*TJ = 8192).
__global__ __launch_bounds__(128)
void occ_reduce_kernel(int N, int NP) {
    const int nK8 = NP >> 3;
    const int t   = blockIdx.x * 128 + threadIdx.x;
    if (t >= NCELL * nK8) return;
    const int c  = t / nK8;
    const int k0 = (t - c * nK8) * 8;

    uint4 aA = make_uint4(0u, 0u, 0u, 0u);
    uint4 aB = make_uint4(0u, 0u, 0u, 0u);
    #pragma unroll 8
    for (int sg = 0; sg < SEG; sg++) {
        const uint4 v = *reinterpret_cast<const uint4*>(
            &g_part[(sg * NCELL + c) * NP + k0]);        // 8 packed u16
        aA.x = __vadd2(aA.x, v.x & 0x00FF00FFu);
        aA.y = __vadd2(aA.y, v.y & 0x00FF00FFu);
        aA.z = __vadd2(aA.z, v.z & 0x00FF00FFu);
        aA.w = __vadd2(aA.w, v.w & 0x00FF00FFu);
        aB.x = __vadd2(aB.x, (v.x >> 8) & 0x00FF00FFu);
        aB.y = __vadd2(aB.y, (v.y >> 8) & 0x00FF00FFu);
        aB.z = __vadd2(aB.z, (v.z >> 8) & 0x00FF00FFu);
        aB.w = __vadd2(aB.w, (v.w >> 8) & 0x00FF00FFu);
    }
    // Agents: iA0..iA0+7 (consecutive) and iA0+64..iA0+71.
    const int iA0 = (k0 >> 6) * 128 + (k0 & 63);
    float4 fa0, fa1, fb0, fb1;
    fa0.x = (float)(aA.x & 0xFFFFu); fa0.y = (float)(aA.x >> 16);
    fa0.z = (float)(aA.y & 0xFFFFu); fa0.w = (float)(aA.y >> 16);
    fa1.x = (float)(aA.z & 0xFFFFu); fa1.y = (float)(aA.z >> 16);
    fa1.z = (float)(aA.w & 0xFFFFu); fa1.w = (float)(aA.w >> 16);
    fb0.x = (float)(aB.x & 0xFFFFu); fb0.y = (float)(aB.x >> 16);
    fb0.z = (float)(aB.y & 0xFFFFu); fb0.w = (float)(aB.y >> 16);
    fb1.x = (float)(aB.z & 0xFFFFu); fb1.y = (float)(aB.z >> 16);
    fb1.z = (float)(aB.w & 0xFFFFu); fb1.w = (float)(aB.w >> 16);
    *reinterpret_cast<float4*>(&g_occ[c * N + iA0])          = fa0;
    *reinterpret_cast<float4*>(&g_occ[c * N + iA0 + 4])      = fa1;
    *reinterpret_cast<float4*>(&g_occ[c * N + iA0 + 64])     = fb0;
    *reinterpret_cast<float4*>(&g_occ[c * N + iA0 + 64 + 4]) = fb1;
}

// Generic-N fallback reduction (scalar, bounds-guarded).
__global__ __launch_bounds__(256)
void occ_reduce_generic(int N, int NP) {
    const int t = blockIdx.x * 256 + threadIdx.x;
    if (t >= NCELL * NP) return;
    const int c = t / NP;
    const int k = t - c * NP;
    unsigned sA = 0, sB = 0;
    #pragma unroll 8
    for (int sg = 0; sg < SEG; sg++) {
        const unsigned v = g_part[(sg * NCELL + c) * NP + k];
        sA += v & 0xFFu;
        sB += (v >> 8) & 0xFFu;
    }
    const int iA = (k >> 6) * 128 + (k & 63);
    const int iB = iA + 64;
    if (iA < N) g_occ[c * N + iA] = (float)sA;
    if (iB < N) g_occ[c * N + iB] = (float)sB;
}

// [N,36] x [36,128] GEMM with smem-staged W and broadcast occ reads.
__global__ __launch_bounds__(256)
void occ_gemm_kernel(const float2* __restrict__ obs,
                     const float*  __restrict__ W,
                     const float*  __restrict__ b,
                     float*        __restrict__ out, int N) {
    __shared__ float sW[HID * 37];                   // stride 37: 5h+c mod 32 conflict-free
    __shared__ __align__(16) float occ_s[BI][40];    // row stride 40: float4-aligned
    __shared__ float sself[BI];

    const int tid = threadIdx.x;
    const int i0  = blockIdx.x * BI;

    // Stage W coalesced.
    for (int idx = tid; idx < HID * NCELL; idx += 256) {
        const int h = idx / NCELL;
        sW[h * 37 + (idx - h * NCELL)] = W[idx];
    }
    // Load occ tile (coalesced along i from the [cell][i] layout).
    for (int idx = tid; idx < NCELL * BI; idx += 256) {
        const int c = idx >> 5, l = idx & 31;
        const int i = i0 + l;
        occ_s[l][c] = (i < N) ? g_occ[c * N + i] : 0.f;
    }
    if (tid < BI) {
        const int i = i0 + tid;
        float v = 0.f;
        if (i < N) {
            const float2 p = obs[i];
            if (!isnan(p.x) && !isnan(p.y)) v = 1.f;
        }
        sself[tid] = v;
    }
    __syncthreads();

    const int h = tid & (HID - 1);
    float w[NCELL];
    #pragma unroll
    for (int c = 0; c < NCELL; c++) w[c] = sW[h * 37 + c];
    const float bias = b[h];

    const int il0 = (tid >> 7) * (BI / 2);
    #pragma unroll
    for (int r = 0; r < BI / 2; r++) {
        const int il = il0 + r;
        const int i  = i0 + il;
        if (i >= N) break;
        // Self-pair was counted at cell 21 iff agent i is finite; remove it.
        float acc = fmaf(-sself[il], w[21], bias);
        const float4* row = (const float4*)&occ_s[il][0];
        #pragma unroll
        for (int c4 = 0; c4 < 9; c4++) {
            const float4 v = row[c4];     // broadcast LDS.128
            acc = fmaf(v.x, w[c4 * 4 + 0], acc);
            acc = fmaf(v.y, w[c4 * 4 + 1], acc);
            acc = fmaf(v.z, w[c4 * 4 + 2], acc);
            acc = fmaf(v.w, w[c4 * 4 + 3], acc);
        }
        out[i * HID + h] = acc;
    }
}

extern "C" void kernel_launch(void* const* d_in, const int* in_sizes, int n_in,
                              void* d_out, int out_size) {
    const float2* obs = (const float2*)d_in[0];
    const float*  W   = (const float*)d_in[1];
    const float*  b   = (const float*)d_in[2];
    float*        out = (float*)d_out;
    const int N  = in_sizes[0] / 2;
    const int GX = (N + APB - 1) / APB;
    const int NP = GX * NT;                // pair slots

    if (N == MAXN) {
        dim3 g1(GX, SEG);
        occ_pair_kernel<true><<<g1, NT>>>(obs, N, NP);
    } else {
        dim3 g1(GX, SEG);
        occ_pair_kernel<false><<<g1, NT>>>(obs, N, NP);
    }
    if ((N & 127) == 0) {
        const int rthreads = NCELL * (NP >> 3);
        occ_reduce_kernel<<<(rthreads + 127) / 128, 128>>>(N, NP);
    } else {
        const int rthreads = NCELL * NP;
        occ_reduce_generic<<<(rthreads + 255) / 256, 256>>>(N, NP);
    }
    occ_gemm_kernel<<<(N + BI - 1) / BI, 256>>>(obs, W, b, out, N);
}

// round 11
// speedup vs baseline: 1.1144x; 1.0768x over previous
#include <cuda_runtime.h>
#include <math.h>

#define GN     6
#define GC     7       // clamped grid side (row/col 6 = trash)
#define NROW   (GC*GC) // 49 histogram rows
#define NCELL  36
#define HID    128
#define NT     64      // threads per block (pair kernel)
#define APB    (2*NT)  // agents per block = 128 (2 per thread)
#define SEG    64      // j-segments -> grid 4096 when N=8192
#define TJ     128     // j tile size; counts per segment <= 128 -> fit in u8
#define MAXN   8192
#define BI     16      // rows per block in GEMM kernel (512 blocks at N=8192)

// Packed partials: [seg][cell][k] u16 = (countA:u8) | (countB:u8 << 8),
// where pair k -> agents iA = (k>>6)*128 + (k&63), iB = iA + 64.
__device__ unsigned short g_part[SEG * NCELL * (MAXN / 2)];
// Reduced occupancy, transposed float: [cell][i]
__device__ float g_occ[NCELL * MAXN];

// rx, ry are precombined grid coords (tile holds 2*xj+3; thread holds -2*xi; one
// FADD joins them). Clamp-grid trash: min((unsigned)floor, 6) sends every invalid
// coordinate (negative -> unsigned-huge, >=6, or saturated F2I from the +1e30
// sentinels) to row/col 6. No predicates, no branches.
// Histogram u32, conflict-free (bank = tid%32): agent A at bit 0, agent B at
// bit 16; per-segment counts <= 128 so each field stays within 8 bits.
__device__ __forceinline__ void bump(unsigned* occ, int tid, float rx, float ry,
                                     unsigned inc) {
    unsigned ix = umin((unsigned)__float2int_rd(rx), (unsigned)(GC - 1));
    unsigned iy = umin((unsigned)__float2int_rd(ry), (unsigned)(GC - 1));
    occ[(ix * GC + iy) * NT + tid] += inc;
}

template<bool EXACT>
__global__ __launch_bounds__(NT, 16)
void occ_pair_kernel(const float2* __restrict__ obs, int N, int NP) {
    __shared__ __align__(16) float2 tile[TJ];    // holds (2*xj+3, 2*yj+3)
    __shared__ unsigned occ[NROW * NT];

    const int tid = threadIdx.x;
    const int iA  = blockIdx.x * APB + tid;
    const int iB  = iA + NT;
    const int seg = blockIdx.y;
    const int JS  = EXACT ? (MAXN / SEG) : ((N + SEG - 1) / SEG);
    const int j0  = seg * JS;
    const int j1  = EXACT ? (j0 + JS) : min(j0 + JS, N);

    // Hold -2*x_i (exact: *2 exact, negate exact). Invalid -> +1e30 sentinel:
    // all counts land in clamp rows, real cells stay 0.
    float nxA = 1e30f, nyA = 1e30f, nxB = 1e30f, nyB = 1e30f;
    if (iA < N) {
        float2 p = obs[iA];
        if (!isnan(p.x) && !isnan(p.y)) { nxA = -2.0f * p.x; nyA = -2.0f * p.y; }
    }
    if (iB < N) {
        float2 p = obs[iB];
        if (!isnan(p.x) && !isnan(p.y)) { nxB = -2.0f * p.x; nyB = -2.0f * p.y; }
    }

    #pragma unroll
    for (int c = 0; c < NROW; c++) occ[c * NT + tid] = 0;
    __syncthreads();

    for (int jb = j0; jb < j1; jb += TJ) {
        const int nj = EXACT ? TJ : min(TJ, j1 - jb);
        for (int t = tid; t < nj; t += NT) {
            float2 p = obs[jb + t];
            float2 v;
            if (isnan(p.x) || isnan(p.y)) { v.x = 1e30f; v.y = 1e30f; }
            else { v.x = fmaf(p.x, 2.0f, 3.0f); v.y = fmaf(p.y, 2.0f, 3.0f); }
            tile[t] = v;
        }
        __syncthreads();

        // Two j's per LDS.128 broadcast; one FADD per coordinate per pair.
        const float4* t4 = (const float4*)tile;
        const int nj2 = nj >> 1;
        #pragma unroll 4
        for (int jj = 0; jj < nj2; jj++) {
            const float4 q = t4[jj];
            bump(occ, tid, q.x + nxA, q.y + nyA, 1u);
            bump(occ, tid, q.x + nxB, q.y + nyB, 1u << 16);
            bump(occ, tid, q.z + nxA, q.w + nyA, 1u);
            bump(occ, tid, q.z + nxB, q.w + nyB, 1u << 16);
        }
        if (!EXACT && (nj & 1)) {
            const float2 p = tile[nj - 1];
            bump(occ, tid, p.x + nxA, p.y + nyA, 1u);
            bump(occ, tid, p.x + nxB, p.y + nyB, 1u << 16);
        }
        __syncthreads();
    }

    // Store 36 real cells packed: (A count u8) | (B count u8 << 8). OOB agents
    // contributed only to clamp rows, so their real cells are 0 -> safe.
    const int k = blockIdx.x * NT + tid;
    #pragma unroll
    for (int c = 0; c < NCELL; c++) {
        const int row = (c / GN) * GC + (c % GN);
        const unsigned v = occ[row * NT + tid];
        g_part[(seg * NCELL + c) * NP + k] =
            (unsigned short)((v & 0xFFu) | ((v >> 8) & 0xFF00u));
    }
}

// Vector reduction (N % 128 == 0): one thread per (cell, 2 pair-slots).
// 73728 threads at N=8192 -> latency fully hidden; u32 load = 2 packed slots.
// Byte layout of v: [A0, B0, A1, B1] -> A halfwords via & 0x00FF00FF,
// B via (>>8) & 0x00FF00FF; vadd2 halfword sums <= SEG*TJ = 8192, no overflow.
__global__ __launch_bounds__(128)
void occ_reduce_kernel(int N, int NP) {
    const int nK2 = NP >> 1;
    const int t   = blockIdx.x * 128 + threadIdx.x;
    if (t >= NCELL * nK2) return;
    const int c  = t / nK2;
    const int k0 = (t - c * nK2) * 2;

    unsigned aA = 0u, aB = 0u;
    const unsigned* base = reinterpret_cast<const unsigned*>(g_part) + (c * NP + k0) / 2;
    #pragma unroll 16
    for (int sg = 0; sg < SEG; sg++) {
        const unsigned v = base[sg * (NCELL * NP / 2)];
        aA = __vadd2(aA, v & 0x00FF00FFu);
        aB = __vadd2(aB, (v >> 8) & 0x00FF00FFu);
    }
    // Agents: iA0, iA0+1 (consecutive) and iA0+64, iA0+65.
    const int iA0 = (k0 >> 6) * 128 + (k0 & 63);
    float2 fa, fb;
    fa.x = (float)(aA & 0xFFFFu); fa.y = (float)(aA >> 16);
    fb.x = (float)(aB & 0xFFFFu); fb.y = (float)(aB >> 16);
    *reinterpret_cast<float2*>(&g_occ[c * N + iA0])      = fa;
    *reinterpret_cast<float2*>(&g_occ[c * N + iA0 + 64]) = fb;
}

// Generic-N fallback reduction (scalar, bounds-guarded).
__global__ __launch_bounds__(256)
void occ_reduce_generic(int N, int NP) {
    const int t = blockIdx.x * 256 + threadIdx.x;
    if (t >= NCELL * NP) return;
    const int c = t / NP;
    const int k = t - c * NP;
    unsigned sA = 0, sB = 0;
    #pragma unroll 8
    for (int sg = 0; sg < SEG; sg++) {
        const unsigned v = g_part[(sg * NCELL + c) * NP + k];
        sA += v & 0xFFu;
        sB += (v >> 8) & 0xFFu;
    }
    const int iA = (k >> 6) * 128 + (k & 63);
    const int iB = iA + 64;
    if (iA < N) g_occ[c * N + iA] = (float)sA;
    if (iB < N) g_occ[c * N + iB] = (float)sB;
}

// [N,36] x [36,128] GEMM with smem-staged W and broadcast occ reads.
// BI=16 -> 512 blocks: latency hiding via block count.
__global__ __launch_bounds__(256)
void occ_gemm_kernel(const float2* __restrict__ obs,
                     const float*  __restrict__ W,
                     const float*  __restrict__ b,
                     float*        __restrict__ out, int N) {
    __shared__ float sW[HID * 37];                   // stride 37: 5h+c mod 32 conflict-free
    __shared__ __align__(16) float occ_s[BI][40];    // row stride 40: float4-aligned
    __shared__ float sself[BI];

    const int tid = threadIdx.x;
    const int i0  = blockIdx.x * BI;

    // Stage W coalesced.
    for (int idx = tid; idx < HID * NCELL; idx += 256) {
        const int h = idx / NCELL;
        sW[h * 37 + (idx - h * NCELL)] = W[idx];
    }
    // Load occ tile (coalesced along i from the [cell][i] layout).
    for (int idx = tid; idx < NCELL * BI; idx += 256) {
        const int c = idx >> 4, l = idx & (BI - 1);
        const int i = i0 + l;
        occ_s[l][c] = (i < N) ? g_occ[c * N + i] : 0.f;
    }
    if (tid < BI) {
        const int i = i0 + tid;
        float v = 0.f;
        if (i < N) {
            const float2 p = obs[i];
            if (!isnan(p.x) && !isnan(p.y)) v = 1.f;
        }
        sself[tid] = v;
    }
    __syncthreads();

    const int h = tid & (HID - 1);
    float w[NCELL];
    #pragma unroll
    for (int c = 0; c < NCELL; c++) w[c] = sW[h * 37 + c];
    const float bias = b[h];

    const int il0 = (tid >> 7) * (BI / 2);
    #pragma unroll
    for (int r = 0; r < BI / 2; r++) {
        const int il = il0 + r;
        const int i  = i0 + il;
        if (i >= N) break;
        // Self-pair was counted at cell 21 iff agent i is finite; remove it.
        float acc = fmaf(-sself[il], w[21], bias);
        const float4* row = (const float4*)&occ_s[il][0];
        #pragma unroll
        for (int c4 = 0; c4 < 9; c4++) {
            const float4 v = row[c4];     // broadcast LDS.128
            acc = fmaf(v.x, w[c4 * 4 + 0], acc);
            acc = fmaf(v.y, w[c4 * 4 + 1], acc);
            acc = fmaf(v.z, w[c4 * 4 + 2], acc);
            acc = fmaf(v.w, w[c4 * 4 + 3], acc);
        }
        out[i * HID + h] = acc;
    }
}

extern "C" void kernel_launch(void* const* d_in, const int* in_sizes, int n_in,
                              void* d_out, int out_size) {
    const float2* obs = (const float2*)d_in[0];
    const float*  W   = (const float*)d_in[1];
    const float*  b   = (const float*)d_in[2];
    float*        out = (float*)d_out;
    const int N  = in_sizes[0] / 2;
    const int GX = (N + APB - 1) / APB;
    const int NP = GX * NT;                // pair slots

    if (N == MAXN) {
        dim3 g1(GX, SEG);
        occ_pair_kernel<true><<<g1, NT>>>(obs, N, NP);
    } else {
        dim3 g1(GX, SEG);
        occ_pair_kernel<false><<<g1, NT>>>(obs, N, NP);
    }
    if ((N & 127) == 0) {
        const int rthreads = NCELL * (NP >> 1);
        occ_reduce_kernel<<<(rthreads + 127) / 128, 128>>>(N, NP);
    } else {
        const int rthreads = NCELL * NP;
        occ_reduce_generic<<<(rthreads + 255) / 256, 256>>>(N, NP);
    }
    occ_gemm_kernel<<<(N + BI - 1) / BI, 256>>>(obs, W, b, out, N);
}